// round 16
// baseline (speedup 1.0000x reference)
#include <cuda_runtime.h>
#include <cuda_fp16.h>
#include <cstdint>

#define B_TOTAL  8192
#define T_STEPS  512
#define HID      128
#define BM       64      // rows per CTA = 4 warps x 16-row M-tiles
#define NTHREADS 128
#define NKT      9       // k-tiles: 128 h + [x0,x1,bias,0..] tile
#define NNT      16      // n-tiles: N = 128
#define ALPHA_C  0.2f
#define BETA_C   0.7f

// B fragments (f16): one uint4 per (ntp,kt,lane) covering TWO n-tiles:
// {nt=2p.b0, nt=2p.b1, nt=2p+1.b0, nt=2p+1.b1}
#define SB_BYTES (8 * NKT * 32 * 16)   // 36864

__device__ __forceinline__ uint32_t f16x2(float lo, float hi) {
    uint32_t r; asm("cvt.rn.f16x2.f32 %0, %1, %2;" : "=r"(r) : "f"(hi), "f"(lo));
    return r;
}
__device__ __forceinline__ uint32_t tanh2_hw(uint32_t p) {
    uint32_t r; asm("tanh.approx.f16x2 %0, %1;" : "=r"(r) : "r"(p)); return r;
}
// m16n8k16 f16 HMMA with f16 accumulators (2x rate of f32-acc), in place
__device__ __forceinline__ void mma16816_h(uint32_t c[2], const uint32_t a[4],
                                           uint32_t b0, uint32_t b1) {
    asm("mma.sync.aligned.m16n8k16.row.col.f16.f16.f16.f16 "
        "{%0,%1}, {%2,%3,%4,%5}, {%6,%7}, {%0,%1};"
        : "+r"(c[0]), "+r"(c[1])
        : "r"(a[0]), "r"(a[1]), "r"(a[2]), "r"(a[3]), "r"(b0), "r"(b1));
}

extern __shared__ char smem[];

__global__ __launch_bounds__(NTHREADS, 1)
void rnn_kernel(const float* __restrict__ input,   // (B, T, 2)
                const float* __restrict__ W_rec,   // (130, 128)
                const float* __restrict__ b_rec,   // (128)
                const float* __restrict__ W_out,   // (128, 1)
                const float* __restrict__ b_out,   // (1)
                float* __restrict__ out)           // (B)
{
    uint4*  sB  = (uint4*)smem;                    // [ntp][kt][lane]
    float2* sWP = (float2*)(smem + SB_BYTES);      // [nt][tig] wout col pairs

    const int tid  = threadIdx.x;
    const int lane = tid & 31;
    const int wid  = tid >> 5;
    const int tig  = lane & 3;     // col group within fragment
    const int gid  = lane >> 2;    // row group 0..7
    const int bBase = blockIdx.x * BM;

    // ---- build B fragments: W'(k,n) rounded to f16
    // W'(k,n): k<128 -> W_rec[k+2][n]; 128->W_rec[0][n]; 129->W_rec[1][n];
    //          130 -> b_rec[n]; else 0.
    for (int idx = tid; idx < 8 * NKT * 32; idx += NTHREADS) {
        int l   = idx & 31;
        int kt  = (idx >> 5) % NKT;
        int ntp = (idx >> 5) / NKT;
        int kb  = kt * 16 + 2 * (l & 3);
        unsigned short hq[2][4];
        #pragma unroll
        for (int half = 0; half < 2; half++) {
            int n = (2 * ntp + half) * 8 + (l >> 2);
            #pragma unroll
            for (int q = 0; q < 4; q++) {
                int k = kb + (q >> 1) * 8 + (q & 1);
                float v;
                if      (k < 128)  v = W_rec[(k + 2) * HID + n];
                else if (k == 128) v = W_rec[n];
                else if (k == 129) v = W_rec[HID + n];
                else if (k == 130) v = b_rec[n];
                else               v = 0.0f;
                hq[half][q] = __half_as_ushort(__float2half_rn(v));
            }
        }
        uint4 bv;
        bv.x = (uint32_t)hq[0][0] | ((uint32_t)hq[0][1] << 16);
        bv.y = (uint32_t)hq[0][2] | ((uint32_t)hq[0][3] << 16);
        bv.z = (uint32_t)hq[1][0] | ((uint32_t)hq[1][1] << 16);
        bv.w = (uint32_t)hq[1][2] | ((uint32_t)hq[1][3] << 16);
        sB[(ntp * NKT + kt) * 32 + l] = bv;
    }
    if (tid < NNT * 4) {
        int nt = tid >> 2, c = tid & 3;
        sWP[tid] = make_float2(W_out[nt * 8 + 2 * c], W_out[nt * 8 + 2 * c + 1]);
    }
    __syncthreads();

    // ---- per-thread recurrent state ----
    const int r0 = wid * 16 + gid;     // local rows r0 and r0+8
    const int r8 = r0 + 8;
    const long long off0 = (long long)(bBase + r0) * (T_STEPS * 2);
    const long long off8 = (long long)(bBase + r8) * (T_STEPS * 2);
    const float bout = b_out[0];

    float2 x0c = *(const float2*)(input + off0);   // x_0
    float2 x8c = *(const float2*)(input + off8);
    float racc0 = 0.f, racc8 = 0.f, prev0 = 0.f, prev8 = 0.f;
    float oacc0 = 0.f, oacc8 = 0.f;

    const uint32_t ONEH = 0x00003C00u;   // {lo=1.0h (bias slot), hi=0}

    uint32_t a[NKT][4];
    #pragma unroll
    for (int kt = 0; kt < 8; kt++)
        #pragma unroll
        for (int q = 0; q < 4; q++) a[kt][q] = 0u;   // h_{-1} = 0
    a[8][0] = (tig == 0) ? f16x2(x0c.x, x0c.y) : (tig == 1) ? ONEH : 0u;
    a[8][1] = (tig == 0) ? f16x2(x8c.x, x8c.y) : (tig == 1) ? ONEH : 0u;
    a[8][2] = 0u; a[8][3] = 0u;

    for (int t = 0; t < T_STEPS; ++t) {
        float2 x0n = make_float2(0.f, 0.f), x8n = make_float2(0.f, 0.f);
        if (t + 1 < T_STEPS) {
            x0n = *(const float2*)(input + off0 + (long long)(t + 1) * 2);
            x8n = *(const float2*)(input + off8 + (long long)(t + 1) * 2);
        }

        // f16 accumulators: c[nt] = {half2(r0: c0,c1), half2(r8: c0,c1)}
        uint32_t c[NNT][2];
        #pragma unroll
        for (int nt = 0; nt < NNT; nt++) { c[nt][0] = 0u; c[nt][1] = 0u; }

        // GEMM kt-outer: 8 fused loads (16 n-tiles) + 16 f16-acc MMAs per kt
        #pragma unroll
        for (int kt = 0; kt < NKT; kt++) {
            uint4 bv[8];
            const uint4* bp = sB + kt * 32 + lane;
            #pragma unroll
            for (int p = 0; p < 8; p++) bv[p] = bp[p * (NKT * 32)];
            #pragma unroll
            for (int p = 0; p < 8; p++) {
                mma16816_h(c[2 * p],     a[kt], bv[p].x, bv[p].y);
                mma16816_h(c[2 * p + 1], a[kt], bv[p].z, bv[p].w);
            }
        }

        // epilogue: packed tanh -> D IS the next A fragment (zero repack);
        // omega dot in fp32 via H2F converts.
        float pr0 = 0.f, pr8 = 0.f;
        #pragma unroll
        for (int nt = 0; nt < NNT; nt++) {
            uint32_t h0 = tanh2_hw(c[nt][0]);
            uint32_t h1 = tanh2_hw(c[nt][1]);
            float2 f0 = __half22float2(*(__half2*)&h0);
            float2 f8 = __half22float2(*(__half2*)&h1);
            float2 wp = sWP[nt * 4 + tig];
            pr0 += f0.x * wp.x + f0.y * wp.y;
            pr8 += f8.x * wp.x + f8.y * wp.y;
            const int kt = nt >> 1, hh = (nt & 1) << 1;
            a[kt][hh]     = h0;
            a[kt][hh + 1] = h1;
        }
        oacc0 = oacc0 * BETA_C + pr0;
        oacc8 = oacc8 * BETA_C + pr8;
        racc0 = racc0 * BETA_C + prev0 * prev0;  prev0 = x0c.x;
        racc8 = racc8 * BETA_C + prev8 * prev8;  prev8 = x8c.x;

        a[8][0] = (tig == 0) ? f16x2(x0n.x, x0n.y) : (tig == 1) ? ONEH : 0u;
        a[8][1] = (tig == 0) ? f16x2(x8n.x, x8n.y) : (tig == 1) ? ONEH : 0u;
        x0c = x0n; x8c = x8n;
    }

    // reduce omega across the 4 col-group lanes of each quad
    oacc0 += __shfl_xor_sync(0xffffffffu, oacc0, 1);
    oacc0 += __shfl_xor_sync(0xffffffffu, oacc0, 2);
    oacc8 += __shfl_xor_sync(0xffffffffu, oacc8, 1);
    oacc8 += __shfl_xor_sync(0xffffffffu, oacc8, 2);

    if (tig == 0) {
        const float geo = 1.0f / (1.0f - BETA_C);   // beta^512 underflows
        out[bBase + r0] = racc0 * ALPHA_C + oacc0 + bout * geo;
        out[bBase + r8] = racc8 * ALPHA_C + oacc8 + bout * geo;
    }
}

extern "C" void kernel_launch(void* const* d_in, const int* in_sizes, int n_in,
                              void* d_out, int out_size) {
    const float* input = (const float*)d_in[0];
    const float* W_rec = (const float*)d_in[1];
    const float* b_rec = (const float*)d_in[2];
    const float* W_out = (const float*)d_in[3];
    const float* b_out = (const float*)d_in[4];
    float* out = (float*)d_out;

    const size_t smem_bytes = SB_BYTES + NNT * 4 * sizeof(float2);  // 37376
    cudaFuncSetAttribute(rnn_kernel, cudaFuncAttributeMaxDynamicSharedMemorySize,
                         (int)smem_bytes);

    rnn_kernel<<<B_TOTAL / BM, NTHREADS, smem_bytes>>>(input, W_rec, b_rec,
                                                       W_out, b_out, out);
    (void)in_sizes; (void)n_in; (void)out_size;
}